// round 2
// baseline (speedup 1.0000x reference)
#include <cuda_runtime.h>
#include <math.h>

#define NB   32      // batch
#define NC   512     // channels
#define HW   4096    // 64*64
#define NSEG 129     // segment ids 0..128 (0 dropped later)
#define NSG  128     // kept segments
#define NCLS 19
#define ATTH 512

// ---- scratch (device globals; no allocation allowed) ----
__device__ int   g_ids[NB * HW];
__device__ float g_invc[NB * NSEG];
__device__ float g_means[NB * NSG * NC];   // 8 MB, row = b*128+seg, col = c
__device__ float g_att[NB * NSG];

// ============================================================
// Kernel 1: downsample mask -> ids, histogram -> inverse counts,
//           zero the attention-logit accumulator.
// NOTE: mask is int32 on device (JAX default x64-disabled downcasts int64).
// ============================================================
__global__ void prep_kernel(const int* __restrict__ mask) {
    int b = blockIdx.x;
    __shared__ int cnt[NSEG];
    for (int t = threadIdx.x; t < NSEG; t += blockDim.x) cnt[t] = 0;
    __syncthreads();
    const int* mb = mask + (long long)b * 512 * 512;
    for (int p = threadIdx.x; p < HW; p += blockDim.x) {
        int i = p >> 6, j = p & 63;
        int id = mb[(i * 8) * 512 + j * 8];
        id = min(max(id, 0), NSEG - 1);   // safety clamp
        g_ids[b * HW + p] = id;
        atomicAdd(&cnt[id], 1);
    }
    __syncthreads();
    for (int t = threadIdx.x; t < NSEG; t += blockDim.x) {
        int cv = cnt[t];
        g_invc[b * NSEG + t] = (t >= 1 && cv > 0) ? (1.0f / (float)cv) : 0.0f;
    }
    for (int t = threadIdx.x; t < NSG; t += blockDim.x) g_att[b * NSG + t] = 0.0f;
}

// ============================================================
// Kernel 2: segment sums via shared-memory atomics, write means.
// Grid: (16 channel-chunks, NB batches). Block: 256 threads.
// Shared accumulator layout s[c][seg] (stride 129, coprime to 32
// -> distinct-segment lanes hit distinct banks).
// ============================================================
__global__ void seg_kernel(const float* __restrict__ x) {
    int b = blockIdx.y;
    int cbase = blockIdx.x * 32;
    __shared__ float s[32 * NSEG];
    __shared__ float invc[NSEG];
    for (int t = threadIdx.x; t < 32 * NSEG; t += 256) s[t] = 0.0f;
    for (int t = threadIdx.x; t < NSEG; t += 256) invc[t] = g_invc[b * NSEG + t];
    __syncthreads();

    int warp = threadIdx.x >> 5, lane = threadIdx.x & 31;
    const float4* x4 = (const float4*)x;
    const int4* id4 = (const int4*)(g_ids + b * HW);

    // each warp owns 512 pixels, processed in 4 groups of 128 (float4 per lane)
    #pragma unroll
    for (int g = 0; g < 4; ++g) {
        int p4 = warp * 128 + g * 32 + lane;   // index in units of float4 (4 pixels)
        int4 id = id4[p4];
        #pragma unroll 4
        for (int c = 0; c < 32; ++c) {
            float4 v = x4[(b * NC + cbase + c) * (HW / 4) + p4];
            float* sc = s + c * NSEG;
            atomicAdd(sc + id.x, v.x);
            atomicAdd(sc + id.y, v.y);
            atomicAdd(sc + id.z, v.z);
            atomicAdd(sc + id.w, v.w);
        }
    }
    __syncthreads();

    // write normalized means (drop segment 0)
    for (int t = threadIdx.x; t < NSG * 32; t += 256) {
        int c = t & 31, sm1 = t >> 5;
        g_means[(b * NSG + sm1) * NC + cbase + c] = s[c * NSEG + sm1 + 1] * invc[sm1 + 1];
    }
}

// ============================================================
// Kernel 3: hidden = relu(means @ Wa1 + ba1); att_logit[row] +=
//           hidden_tile @ Wa2  (hidden never stored).
// M=4096, N=512, K=512. BM=BN=64, BK=16, 4x4 microtile, 256 thr.
// ============================================================
#define BM 64
#define BN 64
#define BK 16

__global__ void att_gemm_kernel(const float* __restrict__ Wa1,
                                const float* __restrict__ ba1,
                                const float* __restrict__ Wa2) {
    int mbase = blockIdx.y * BM;
    int nbase = blockIdx.x * BN;
    __shared__ float Ast[BK][BM + 4];  // transposed A tile, padded
    __shared__ float Bs[BK][BN];
    __shared__ float attred[BM];

    int tid = threadIdx.x;
    int tx = tid & 15, ty = tid >> 4;
    int aRow = tid >> 2, aK = (tid & 3) * 4;
    int bK = tid >> 4, bCol = (tid & 15) * 4;

    float acc[4][4] = {};

    for (int k0 = 0; k0 < NC; k0 += BK) {
        float4 av = *(const float4*)&g_means[(mbase + aRow) * NC + k0 + aK];
        float4 bv = *(const float4*)&Wa1[(k0 + bK) * ATTH + nbase + bCol];
        Ast[aK + 0][aRow] = av.x;
        Ast[aK + 1][aRow] = av.y;
        Ast[aK + 2][aRow] = av.z;
        Ast[aK + 3][aRow] = av.w;
        *(float4*)&Bs[bK][bCol] = bv;
        __syncthreads();
        #pragma unroll
        for (int kk = 0; kk < BK; ++kk) {
            float4 a = *(const float4*)&Ast[kk][ty * 4];
            float4 bb = *(const float4*)&Bs[kk][tx * 4];
            acc[0][0] += a.x * bb.x; acc[0][1] += a.x * bb.y;
            acc[0][2] += a.x * bb.z; acc[0][3] += a.x * bb.w;
            acc[1][0] += a.y * bb.x; acc[1][1] += a.y * bb.y;
            acc[1][2] += a.y * bb.z; acc[1][3] += a.y * bb.w;
            acc[2][0] += a.z * bb.x; acc[2][1] += a.z * bb.y;
            acc[2][2] += a.z * bb.z; acc[2][3] += a.z * bb.w;
            acc[3][0] += a.w * bb.x; acc[3][1] += a.w * bb.y;
            acc[3][2] += a.w * bb.z; acc[3][3] += a.w * bb.w;
        }
        __syncthreads();
    }

    if (tid < BM) attred[tid] = 0.0f;
    __syncthreads();

    float w2[4], b1[4];
    #pragma unroll
    for (int j = 0; j < 4; ++j) {
        int n = nbase + tx * 4 + j;
        w2[j] = Wa2[n];
        b1[j] = ba1[n];
    }
    #pragma unroll
    for (int i = 0; i < 4; ++i) {
        float part = 0.0f;
        #pragma unroll
        for (int j = 0; j < 4; ++j) {
            float h = fmaxf(acc[i][j] + b1[j], 0.0f);
            part += h * w2[j];
        }
        atomicAdd(&attred[ty * 4 + i], part);
    }
    __syncthreads();
    if (tid < BM) atomicAdd(&g_att[mbase + tid], attred[tid]);
}

// ============================================================
// Kernel 4: per-batch softmax over 128 att logits, weighted mean
// over segments, then (wm @ Wh + bh) -> logits.
// (Uses linearity: sum_s att*(m@Wh+bh) == (sum_s att*m)@Wh + bh.)
// ============================================================
__global__ void final_kernel(const float* __restrict__ Wh,
                             const float* __restrict__ bh,
                             const float* __restrict__ ba2,
                             float* __restrict__ out) {
    int b = blockIdx.x;
    int t = threadIdx.x;
    __shared__ float satt[NSG];
    __shared__ float swm[NC];
    __shared__ float sred[2];

    if (t < NSG) satt[t] = g_att[b * NSG + t] + ba2[0];
    __syncthreads();
    if (t < 32) {
        float m = fmaxf(fmaxf(satt[t], satt[t + 32]), fmaxf(satt[t + 64], satt[t + 96]));
        #pragma unroll
        for (int o = 16; o > 0; o >>= 1) m = fmaxf(m, __shfl_xor_sync(0xffffffffu, m, o));
        sred[0] = m;
    }
    __syncthreads();
    float mx = sred[0];
    if (t < NSG) satt[t] = expf(satt[t] - mx);
    __syncthreads();
    if (t < 32) {
        float sm = satt[t] + satt[t + 32] + satt[t + 64] + satt[t + 96];
        #pragma unroll
        for (int o = 16; o > 0; o >>= 1) sm += __shfl_xor_sync(0xffffffffu, sm, o);
        sred[1] = sm;
    }
    __syncthreads();
    float inv = 1.0f / sred[1];
    if (t < NSG) satt[t] *= inv;
    __syncthreads();

    // weighted mean over segments: thread t = channel
    {
        float wm = 0.0f;
        const float* mp = g_means + b * NSG * NC + t;
        #pragma unroll 8
        for (int s = 0; s < NSG; ++s) wm += satt[s] * mp[s * NC];
        swm[t] = wm;
    }
    __syncthreads();

    if (t < NCLS) {
        float acc = bh[t];
        #pragma unroll 8
        for (int c = 0; c < NC; ++c) acc += swm[c] * Wh[c * NCLS + t];
        out[b * NCLS + t] = acc;
    }
}

// ============================================================
// Kernel 5: BCE-with-logits loss, mean over all 608 elements.
// ============================================================
__global__ void loss_kernel(const float* __restrict__ target,
                            float* __restrict__ out, int out_size) {
    const int n = NB * NCLS;   // 608
    int t = threadIdx.x;
    float v = 0.0f;
    if (t < n) {
        float l = out[t];
        float tg = target[t];
        v = fmaxf(l, 0.0f) - l * tg + log1pf(expf(-fabsf(l)));
    }
    __shared__ float red[32];
    int lane = t & 31, warp = t >> 5;
    #pragma unroll
    for (int o = 16; o > 0; o >>= 1) v += __shfl_xor_sync(0xffffffffu, v, o);
    if (lane == 0) red[warp] = v;
    __syncthreads();
    if (t < 32) {
        float s = (t < 20) ? red[t] : 0.0f;
        #pragma unroll
        for (int o = 16; o > 0; o >>= 1) s += __shfl_xor_sync(0xffffffffu, s, o);
        if (t == 0) out[out_size - 1] = s / (float)n;
    }
}

// ============================================================
extern "C" void kernel_launch(void* const* d_in, const int* in_sizes, int n_in,
                              void* d_out, int out_size) {
    const float* x      = (const float*)d_in[0];
    const int*   mask   = (const int*)d_in[1];
    const float* target = (const float*)d_in[2];
    const float* Wa1    = (const float*)d_in[3];
    const float* ba1    = (const float*)d_in[4];
    const float* Wa2    = (const float*)d_in[5];
    const float* ba2    = (const float*)d_in[6];
    const float* Wh     = (const float*)d_in[7];
    const float* bh     = (const float*)d_in[8];
    float* out = (float*)d_out;

    prep_kernel<<<NB, 256>>>(mask);
    seg_kernel<<<dim3(16, NB), 256>>>(x);
    att_gemm_kernel<<<dim3(ATTH / BN, (NB * NSG) / BM), 256>>>(Wa1, ba1, Wa2);
    final_kernel<<<NB, NC>>>(Wh, bh, ba2, out);
    loss_kernel<<<1, 640>>>(target, out, out_size);
}

// round 3
// speedup vs baseline: 1.3346x; 1.3346x over previous
#include <cuda_runtime.h>
#include <math.h>

#define NB   32      // batch
#define NC   512     // channels
#define HW   4096    // 64*64
#define NSEG 129     // segment ids 0..128 (0 dropped later)
#define NSG  128     // kept segments
#define NCLS 19
#define ATTH 512

typedef unsigned long long u64;

#define FMA_F32X2(d, a, b, c) \
    asm("fma.rn.f32x2 %0, %1, %2, %3;" : "=l"(d) : "l"(a), "l"(b), "l"(c))
#define PACK_DUP_F32X2(d, s) \
    asm("mov.b64 %0, {%1, %1};" : "=l"(d) : "r"(__float_as_uint(s)))
#define UNPACK_F32X2(lo, hi, in) \
    asm("mov.b64 {%0, %1}, %2;" : "=r"(lo), "=r"(hi) : "l"(in))

// ---- scratch (device globals; no allocation allowed) ----
__device__ int   g_ids[NB * HW];
__device__ float g_invc[NB * NSEG];
__device__ float g_means[NB * NSG * NC];   // 8 MB, row = b*128+seg, col = c
__device__ float g_att[NB * NSG];
__device__ float g_attw[NB * NSG];

// ============================================================
// Kernel 1: downsample mask -> ids, histogram -> inverse counts,
//           zero att accumulator, init out logits with bh.
// ============================================================
__global__ void prep_kernel(const int* __restrict__ mask,
                            const float* __restrict__ bh,
                            float* __restrict__ out) {
    int b = blockIdx.x;
    __shared__ int cnt[NSEG];
    for (int t = threadIdx.x; t < NSEG; t += blockDim.x) cnt[t] = 0;
    __syncthreads();
    const int* mb = mask + (long long)b * 512 * 512;
    for (int p = threadIdx.x; p < HW; p += blockDim.x) {
        int i = p >> 6, j = p & 63;
        int id = mb[(i * 8) * 512 + j * 8];
        id = min(max(id, 0), NSEG - 1);   // safety clamp
        g_ids[b * HW + p] = id;
        atomicAdd(&cnt[id], 1);
    }
    __syncthreads();
    for (int t = threadIdx.x; t < NSEG; t += blockDim.x) {
        int cv = cnt[t];
        g_invc[b * NSEG + t] = (t >= 1 && cv > 0) ? (1.0f / (float)cv) : 0.0f;
    }
    for (int t = threadIdx.x; t < NSG; t += blockDim.x) g_att[b * NSG + t] = 0.0f;
    if (threadIdx.x < NCLS) out[b * NCLS + threadIdx.x] = bh[threadIdx.x];
}

// ============================================================
// Kernel 2: segment sums WITHOUT atomics.
// Block = (32-channel chunk, batch), 256 threads (8 warps).
// Per 128-pixel tile: stage x (coalesced) into s_tile[c][p]
// (stride 129 -> transposed read conflict-free). Warp w owns all
// segment ids with id%8 == w (found via ballot), so the
// accumulator RMW s_acc[id][lane] (stride 33, lanes=channels) is
// race-free and bank-conflict-free with zero atomics.
// ============================================================
__global__ void seg_kernel(const float* __restrict__ x) {
    int b = blockIdx.y;
    int cbase = blockIdx.x * 32;
    __shared__ float s_tile[32 * 129];   // [channel][pixel-in-tile]
    __shared__ float s_acc[NSEG * 33];   // [id][channel]

    int tid = threadIdx.x;
    int w = tid >> 5, lane = tid & 31;

    for (int t = tid; t < NSEG * 33; t += 256) s_acc[t] = 0.0f;

    const float4* x4 = (const float4*)x;
    long long xbase = (long long)(b * NC + cbase) * (HW / 4);
    int cf = tid >> 3, qf = tid & 7;     // fill mapping: channel, f4-slot
    const int* idsb = g_ids + b * HW;

    for (int tile = 0; tile < 32; ++tile) {
        __syncthreads();   // prior RMW done (and acc-zero on first iter)
        // stage 32ch x 128px (32 float4 per channel row)
        #pragma unroll
        for (int k = 0; k < 4; ++k) {
            int f4 = qf + 8 * k;
            float4 v = x4[xbase + (long long)cf * (HW / 4) + tile * 32 + f4];
            int o = cf * 129 + f4 * 4;
            s_tile[o + 0] = v.x; s_tile[o + 1] = v.y;
            s_tile[o + 2] = v.z; s_tile[o + 3] = v.w;
        }
        __syncthreads();
        // scatter: warp w handles ids with (id & 7) == w
        #pragma unroll
        for (int g = 0; g < 4; ++g) {
            int idl = idsb[tile * 128 + g * 32 + lane];
            unsigned m = __ballot_sync(0xffffffffu, (idl & 7) == w);
            while (m) {
                int j = __ffs(m) - 1;
                m &= (m - 1);
                int id = __shfl_sync(0xffffffffu, idl, j);
                float v = s_tile[lane * 129 + g * 32 + j];
                s_acc[id * 33 + lane] += v;
            }
        }
    }
    __syncthreads();

    // write normalized means (drop segment 0)
    for (int t = tid; t < NSG * 32; t += 256) {
        int c = t & 31, sm1 = t >> 5;
        g_means[((long long)b * NSG + sm1) * NC + cbase + c] =
            s_acc[(sm1 + 1) * 33 + c] * g_invc[b * NSEG + sm1 + 1];
    }
}

// ============================================================
// Kernel 3: att logits. hidden = relu(means @ Wa1 + ba1);
// g_att[m] += hidden_tile @ Wa2 (hidden never stored).
// M=4096, N=512, K=512. BM=128, BN=64, BK=16, 256 thr,
// 8m x 4n microtile using packed fma.rn.f32x2 (m-pairs).
// ============================================================
#define BM 128
#define BN 64
#define BK 16

__global__ void att_gemm_kernel(const float* __restrict__ Wa1,
                                const float* __restrict__ ba1,
                                const float* __restrict__ Wa2) {
    int mbase = blockIdx.y * BM;
    int nbase = blockIdx.x * BN;
    __shared__ float Ast[BK * (BM + 4)];   // transposed A, row stride 132
    __shared__ float Bs[BK * BN];

    int tid = threadIdx.x;
    int tx = tid & 15, ty = tid >> 4;          // n = tx*4, m = ty*8
    int aRow = tid >> 1, aK = (tid & 1) * 8;   // A fill: 128 rows x 2 halves
    int bK = tid >> 4, bCol = (tid & 15) * 4;  // B fill

    u64 acc2[4][4];
    #pragma unroll
    for (int i = 0; i < 4; ++i)
        #pragma unroll
        for (int j = 0; j < 4; ++j) acc2[i][j] = 0ULL;

    for (int k0 = 0; k0 < NC; k0 += BK) {
        float4 a0 = *(const float4*)&g_means[(long long)(mbase + aRow) * NC + k0 + aK];
        float4 a1 = *(const float4*)&g_means[(long long)(mbase + aRow) * NC + k0 + aK + 4];
        float4 bv = *(const float4*)&Wa1[(long long)(k0 + bK) * ATTH + nbase + bCol];
        Ast[(aK + 0) * 132 + aRow] = a0.x;
        Ast[(aK + 1) * 132 + aRow] = a0.y;
        Ast[(aK + 2) * 132 + aRow] = a0.z;
        Ast[(aK + 3) * 132 + aRow] = a0.w;
        Ast[(aK + 4) * 132 + aRow] = a1.x;
        Ast[(aK + 5) * 132 + aRow] = a1.y;
        Ast[(aK + 6) * 132 + aRow] = a1.z;
        Ast[(aK + 7) * 132 + aRow] = a1.w;
        *(float4*)&Bs[bK * BN + bCol] = bv;
        __syncthreads();
        #pragma unroll
        for (int kk = 0; kk < BK; ++kk) {
            u64 a2[4];
            #pragma unroll
            for (int mp = 0; mp < 4; ++mp)
                a2[mp] = *(const u64*)&Ast[kk * 132 + ty * 8 + 2 * mp];
            float4 b4 = *(const float4*)&Bs[kk * BN + tx * 4];
            u64 bd[4];
            PACK_DUP_F32X2(bd[0], b4.x);
            PACK_DUP_F32X2(bd[1], b4.y);
            PACK_DUP_F32X2(bd[2], b4.z);
            PACK_DUP_F32X2(bd[3], b4.w);
            #pragma unroll
            for (int mp = 0; mp < 4; ++mp) {
                FMA_F32X2(acc2[mp][0], a2[mp], bd[0], acc2[mp][0]);
                FMA_F32X2(acc2[mp][1], a2[mp], bd[1], acc2[mp][1]);
                FMA_F32X2(acc2[mp][2], a2[mp], bd[2], acc2[mp][2]);
                FMA_F32X2(acc2[mp][3], a2[mp], bd[3], acc2[mp][3]);
            }
        }
        __syncthreads();
    }

    // epilogue: relu(acc + ba1) dot Wa2, reduce across the 16 tx lanes
    float b1[4], w2[4];
    #pragma unroll
    for (int j = 0; j < 4; ++j) {
        int n = nbase + tx * 4 + j;
        b1[j] = ba1[n];
        w2[j] = Wa2[n];
    }
    #pragma unroll
    for (int mp = 0; mp < 4; ++mp) {
        float p0 = 0.0f, p1 = 0.0f;
        #pragma unroll
        for (int j = 0; j < 4; ++j) {
            unsigned lo, hi;
            UNPACK_F32X2(lo, hi, acc2[mp][j]);
            float h0 = fmaxf(__uint_as_float(lo) + b1[j], 0.0f);
            float h1 = fmaxf(__uint_as_float(hi) + b1[j], 0.0f);
            p0 += h0 * w2[j];
            p1 += h1 * w2[j];
        }
        #pragma unroll
        for (int o = 8; o > 0; o >>= 1) {
            p0 += __shfl_xor_sync(0xffffffffu, p0, o);
            p1 += __shfl_xor_sync(0xffffffffu, p1, o);
        }
        if (tx == 0) {
            atomicAdd(&g_att[mbase + ty * 8 + 2 * mp + 0], p0);
            atomicAdd(&g_att[mbase + ty * 8 + 2 * mp + 1], p1);
        }
    }
}

// ============================================================
// Kernel 4: per-batch softmax over 128 att logits -> g_attw.
// ============================================================
__global__ void att_softmax_kernel(const float* __restrict__ ba2) {
    int b = blockIdx.x, t = threadIdx.x;   // 128 threads
    __shared__ float red[4];
    float v = g_att[b * NSG + t] + ba2[0];
    float m = v;
    #pragma unroll
    for (int o = 16; o > 0; o >>= 1) m = fmaxf(m, __shfl_xor_sync(0xffffffffu, m, o));
    if ((t & 31) == 0) red[t >> 5] = m;
    __syncthreads();
    m = fmaxf(fmaxf(red[0], red[1]), fmaxf(red[2], red[3]));
    float e = expf(v - m);
    float s = e;
    #pragma unroll
    for (int o = 16; o > 0; o >>= 1) s += __shfl_xor_sync(0xffffffffu, s, o);
    __syncthreads();
    if ((t & 31) == 0) red[t >> 5] = s;
    __syncthreads();
    s = red[0] + red[1] + red[2] + red[3];
    g_attw[b * NSG + t] = e / s;
}

// ============================================================
// Kernel 5: weighted mean over segments + partial class dots.
// Grid (4 channel-groups, 32 batches), 128 threads.
// Uses linearity: sum_s att*(m@Wh+bh) == (sum_s att*m)@Wh + bh.
// out logits pre-initialized to bh by prep; atomicAdd partials.
// ============================================================
__global__ void wm_kernel(const float* __restrict__ Wh,
                          float* __restrict__ out) {
    int b = blockIdx.y, cg = blockIdx.x, t = threadIdx.x;
    int c = cg * 128 + t;
    __shared__ float satt[NSG];
    satt[t] = g_attw[b * NSG + t];
    __syncthreads();

    float wm = 0.0f;
    const float* mp = g_means + (long long)b * NSG * NC + c;
    #pragma unroll 8
    for (int s = 0; s < NSG; ++s) wm += satt[s] * mp[(long long)s * NC];

    const float* whr = Wh + (long long)c * NCLS;
    #pragma unroll 1
    for (int cls = 0; cls < NCLS; ++cls) {
        float p = wm * whr[cls];
        #pragma unroll
        for (int o = 16; o > 0; o >>= 1) p += __shfl_xor_sync(0xffffffffu, p, o);
        if ((t & 31) == 0) atomicAdd(&out[b * NCLS + cls], p);
    }
}

// ============================================================
// Kernel 6: BCE-with-logits loss, mean over all 608 elements.
// ============================================================
__global__ void loss_kernel(const float* __restrict__ target,
                            float* __restrict__ out, int out_size) {
    const int n = NB * NCLS;   // 608
    int t = threadIdx.x;
    float v = 0.0f;
    if (t < n) {
        float l = out[t];
        float tg = target[t];
        v = fmaxf(l, 0.0f) - l * tg + log1pf(expf(-fabsf(l)));
    }
    __shared__ float red[32];
    int lane = t & 31, warp = t >> 5;
    #pragma unroll
    for (int o = 16; o > 0; o >>= 1) v += __shfl_xor_sync(0xffffffffu, v, o);
    if (lane == 0) red[warp] = v;
    __syncthreads();
    if (t < 32) {
        float s = (t < 20) ? red[t] : 0.0f;
        #pragma unroll
        for (int o = 16; o > 0; o >>= 1) s += __shfl_xor_sync(0xffffffffu, s, o);
        if (t == 0) out[out_size - 1] = s / (float)n;
    }
}

// ============================================================
extern "C" void kernel_launch(void* const* d_in, const int* in_sizes, int n_in,
                              void* d_out, int out_size) {
    const float* x      = (const float*)d_in[0];
    const int*   mask   = (const int*)d_in[1];
    const float* target = (const float*)d_in[2];
    const float* Wa1    = (const float*)d_in[3];
    const float* ba1    = (const float*)d_in[4];
    const float* Wa2    = (const float*)d_in[5];
    const float* ba2    = (const float*)d_in[6];
    const float* Wh     = (const float*)d_in[7];
    const float* bh     = (const float*)d_in[8];
    float* out = (float*)d_out;

    prep_kernel<<<NB, 256>>>(mask, bh, out);
    seg_kernel<<<dim3(16, NB), 256>>>(x);
    att_gemm_kernel<<<dim3(ATTH / BN, (NB * NSG) / BM), 256>>>(Wa1, ba1, Wa2);
    att_softmax_kernel<<<NB, NSG>>>(ba2);
    wm_kernel<<<dim3(4, NB), 128>>>(Wh, out);
    loss_kernel<<<1, 640>>>(target, out, out_size);
}

// round 4
// speedup vs baseline: 1.4601x; 1.0940x over previous
#include <cuda_runtime.h>
#include <math.h>

#define NB   32      // batch
#define NC   512     // channels
#define HW   4096    // 64*64
#define NSEG 129     // segment ids 0..128 (0 dropped later)
#define NSG  128     // kept segments
#define NCLS 19
#define ATTH 512

typedef unsigned long long u64;

#define FMA_F32X2(d, a, b, c) \
    asm("fma.rn.f32x2 %0, %1, %2, %3;" : "=l"(d) : "l"(a), "l"(b), "l"(c))
#define PACK_DUP_F32X2(d, s) \
    asm("mov.b64 %0, {%1, %1};" : "=l"(d) : "r"(__float_as_uint(s)))
#define UNPACK_F32X2(lo, hi, in) \
    asm("mov.b64 {%0, %1}, %2;" : "=r"(lo), "=r"(hi) : "l"(in))

// ---- scratch (device globals; no allocation allowed) ----
__device__ int   g_ids[NB * HW];
__device__ float g_invc[NB * NSEG];
__device__ float g_means[NB * NSG * NC];   // 8 MB, row = b*128+seg, col = c
__device__ float g_att[NB * NSG];

// ============================================================
// Kernel 1: downsample mask -> ids, histogram -> inverse counts.
// ============================================================
__global__ void prep_kernel(const int* __restrict__ mask) {
    int b = blockIdx.x;
    __shared__ int cnt[NSEG];
    for (int t = threadIdx.x; t < NSEG; t += blockDim.x) cnt[t] = 0;
    __syncthreads();
    const int* mb = mask + (long long)b * 512 * 512;
    for (int p = threadIdx.x; p < HW; p += blockDim.x) {
        int i = p >> 6, j = p & 63;
        int id = mb[(i * 8) * 512 + j * 8];
        id = min(max(id, 0), NSEG - 1);   // safety clamp
        g_ids[b * HW + p] = id;
        atomicAdd(&cnt[id], 1);
    }
    __syncthreads();
    for (int t = threadIdx.x; t < NSEG; t += blockDim.x) {
        int cv = cnt[t];
        g_invc[b * NSEG + t] = (t >= 1 && cv > 0) ? (1.0f / (float)cv) : 0.0f;
    }
}

// ============================================================
// Kernel 2 (tiny): zero att accumulator, init out logits = bh.
// ============================================================
__global__ void zero_att_kernel(const float* __restrict__ bh,
                                float* __restrict__ out) {
    int t = blockIdx.x * 256 + threadIdx.x;   // grid 16 -> 4096
    g_att[t] = 0.0f;
    if (t < NB * NCLS) out[t] = bh[t % NCLS];
}

// ============================================================
// Kernel 3: segment sums WITHOUT atomics (ballot id-partition).
// ============================================================
__global__ void seg_kernel(const float* __restrict__ x) {
    int b = blockIdx.y;
    int cbase = blockIdx.x * 32;
    __shared__ float s_tile[32 * 129];   // [channel][pixel-in-tile]
    __shared__ float s_acc[NSEG * 33];   // [id][channel]

    int tid = threadIdx.x;
    int w = tid >> 5, lane = tid & 31;

    for (int t = tid; t < NSEG * 33; t += 256) s_acc[t] = 0.0f;

    const float4* x4 = (const float4*)x;
    long long xbase = (long long)(b * NC + cbase) * (HW / 4);
    int cf = tid >> 3, qf = tid & 7;     // fill mapping: channel, f4-slot
    const int* idsb = g_ids + b * HW;

    for (int tile = 0; tile < 32; ++tile) {
        __syncthreads();   // prior RMW done (and acc-zero on first iter)
        #pragma unroll
        for (int k = 0; k < 4; ++k) {
            int f4 = qf + 8 * k;
            float4 v = x4[xbase + (long long)cf * (HW / 4) + tile * 32 + f4];
            int o = cf * 129 + f4 * 4;
            s_tile[o + 0] = v.x; s_tile[o + 1] = v.y;
            s_tile[o + 2] = v.z; s_tile[o + 3] = v.w;
        }
        __syncthreads();
        #pragma unroll
        for (int g = 0; g < 4; ++g) {
            int idl = idsb[tile * 128 + g * 32 + lane];
            unsigned m = __ballot_sync(0xffffffffu, (idl & 7) == w);
            while (m) {
                int j = __ffs(m) - 1;
                m &= (m - 1);
                int id = __shfl_sync(0xffffffffu, idl, j);
                float v = s_tile[lane * 129 + g * 32 + j];
                s_acc[id * 33 + lane] += v;
            }
        }
    }
    __syncthreads();

    for (int t = tid; t < NSG * 32; t += 256) {
        int c = t & 31, sm1 = t >> 5;
        g_means[((long long)b * NSG + sm1) * NC + cbase + c] =
            s_acc[(sm1 + 1) * 33 + c] * g_invc[b * NSEG + sm1 + 1];
    }
}

// ============================================================
// Kernel 4: att logits GEMM. hidden = relu(means @ Wa1 + ba1);
// g_att[m] += hidden_tile @ Wa2 (hidden never stored).
// BM=128, BN=64, BK=32, double-buffered smem (1 sync/iter),
// 256 thr, 8m x 4n microtile with packed fma.rn.f32x2.
// ============================================================
#define GBM 128
#define GBN 64
#define GBK 32
#define ASTR 130                 // even pad: u64-aligned LDS, benign 2-way STS
#define GEMM_SMEM ((2 * GBK * ASTR + 2 * GBK * GBN) * 4)

__global__ void __launch_bounds__(256, 2)
att_gemm_kernel(const float* __restrict__ Wa1,
                const float* __restrict__ ba1,
                const float* __restrict__ Wa2) {
    extern __shared__ float sm[];
    float* AstBuf = sm;                       // 2 * 32*130
    float* BsBuf  = sm + 2 * GBK * ASTR;      // 2 * 32*64

    int tid = threadIdx.x;
    int mbase = blockIdx.y * GBM;
    int nbase = blockIdx.x * GBN;
    int tx = tid & 15, ty = tid >> 4;         // n = tx*4, m = ty*8

    // fill mappings (coalesced 128B rows)
    int ar = tid >> 3, ak = (tid & 7) * 4;    // A: row ar(+32p), k ak..ak+3
    int br = tid >> 4, bc = (tid & 15) * 4;   // B: k-row br(+16p), n bc..bc+3
    const float* Ag = g_means + (long long)(mbase + ar) * NC + ak;
    const float* Bg = Wa1 + (long long)br * ATTH + nbase + bc;

    u64 acc2[4][4];
    #pragma unroll
    for (int i = 0; i < 4; ++i)
        #pragma unroll
        for (int j = 0; j < 4; ++j) acc2[i][j] = 0ULL;

    float4 pa[4], pb[2];
    #pragma unroll
    for (int p = 0; p < 4; ++p) pa[p] = *(const float4*)(Ag + (long long)(32 * p) * NC);
    #pragma unroll
    for (int p = 0; p < 2; ++p) pb[p] = *(const float4*)(Bg + (long long)(16 * p) * ATTH);

    const int NITER = NC / GBK;   // 16
    int cur = 0;
    #pragma unroll 1
    for (int it = 0; it < NITER; ++it) {
        float* Ac = AstBuf + cur * GBK * ASTR;
        float* Bc = BsBuf + cur * GBK * GBN;
        // store prefetched tile
        #pragma unroll
        for (int p = 0; p < 4; ++p) {
            int row = ar + 32 * p;
            Ac[(ak + 0) * ASTR + row] = pa[p].x;
            Ac[(ak + 1) * ASTR + row] = pa[p].y;
            Ac[(ak + 2) * ASTR + row] = pa[p].z;
            Ac[(ak + 3) * ASTR + row] = pa[p].w;
        }
        #pragma unroll
        for (int p = 0; p < 2; ++p)
            *(float4*)(Bc + (br + 16 * p) * GBN + bc) = pb[p];
        __syncthreads();

        if (it + 1 < NITER) {
            int k0n = (it + 1) * GBK;
            #pragma unroll
            for (int p = 0; p < 4; ++p)
                pa[p] = *(const float4*)(Ag + (long long)(32 * p) * NC + k0n);
            #pragma unroll
            for (int p = 0; p < 2; ++p)
                pb[p] = *(const float4*)(Bg + (long long)(k0n + 16 * p) * ATTH);
        }

        #pragma unroll
        for (int kk = 0; kk < GBK; ++kk) {
            const float* Ak = Ac + kk * ASTR + ty * 8;
            u64 a2[4];
            a2[0] = *(const u64*)(Ak + 0);
            a2[1] = *(const u64*)(Ak + 2);
            a2[2] = *(const u64*)(Ak + 4);
            a2[3] = *(const u64*)(Ak + 6);
            float4 b4 = *(const float4*)(Bc + kk * GBN + tx * 4);
            u64 bd[4];
            PACK_DUP_F32X2(bd[0], b4.x);
            PACK_DUP_F32X2(bd[1], b4.y);
            PACK_DUP_F32X2(bd[2], b4.z);
            PACK_DUP_F32X2(bd[3], b4.w);
            #pragma unroll
            for (int mp = 0; mp < 4; ++mp) {
                FMA_F32X2(acc2[mp][0], a2[mp], bd[0], acc2[mp][0]);
                FMA_F32X2(acc2[mp][1], a2[mp], bd[1], acc2[mp][1]);
                FMA_F32X2(acc2[mp][2], a2[mp], bd[2], acc2[mp][2]);
                FMA_F32X2(acc2[mp][3], a2[mp], bd[3], acc2[mp][3]);
            }
        }
        cur ^= 1;
    }

    // epilogue: relu(acc + ba1) dot Wa2, reduce across the 16 tx lanes
    float b1[4], w2[4];
    #pragma unroll
    for (int j = 0; j < 4; ++j) {
        int n = nbase + tx * 4 + j;
        b1[j] = ba1[n];
        w2[j] = Wa2[n];
    }
    #pragma unroll
    for (int mp = 0; mp < 4; ++mp) {
        float p0 = 0.0f, p1 = 0.0f;
        #pragma unroll
        for (int j = 0; j < 4; ++j) {
            unsigned lo, hi;
            UNPACK_F32X2(lo, hi, acc2[mp][j]);
            float h0 = fmaxf(__uint_as_float(lo) + b1[j], 0.0f);
            float h1 = fmaxf(__uint_as_float(hi) + b1[j], 0.0f);
            p0 += h0 * w2[j];
            p1 += h1 * w2[j];
        }
        #pragma unroll
        for (int o = 8; o > 0; o >>= 1) {
            p0 += __shfl_xor_sync(0xffffffffu, p0, o);
            p1 += __shfl_xor_sync(0xffffffffu, p1, o);
        }
        if (tx == 0) {
            atomicAdd(&g_att[mbase + ty * 8 + 2 * mp + 0], p0);
            atomicAdd(&g_att[mbase + ty * 8 + 2 * mp + 1], p1);
        }
    }
}

// ============================================================
// Kernel 5: fused softmax + weighted mean + partial class dots.
// Grid (4 channel-groups, 32 batches), 128 threads. Softmax over
// the 128 logits recomputed redundantly per block (cheap).
// ============================================================
__global__ void wm_kernel(const float* __restrict__ Wh,
                          const float* __restrict__ ba2,
                          float* __restrict__ out) {
    int b = blockIdx.y, cg = blockIdx.x, t = threadIdx.x;
    int lane = t & 31, w = t >> 5;
    __shared__ float satt[NSG];
    __shared__ float red[4];

    float v = g_att[b * NSG + t] + ba2[0];
    float m = v;
    #pragma unroll
    for (int o = 16; o > 0; o >>= 1) m = fmaxf(m, __shfl_xor_sync(0xffffffffu, m, o));
    if (lane == 0) red[w] = m;
    __syncthreads();
    m = fmaxf(fmaxf(red[0], red[1]), fmaxf(red[2], red[3]));
    float e = expf(v - m);
    float s = e;
    #pragma unroll
    for (int o = 16; o > 0; o >>= 1) s += __shfl_xor_sync(0xffffffffu, s, o);
    __syncthreads();
    if (lane == 0) red[w] = s;
    __syncthreads();
    s = red[0] + red[1] + red[2] + red[3];
    satt[t] = e / s;
    __syncthreads();

    int c = cg * 128 + t;
    float wm = 0.0f;
    const float* mp = g_means + (long long)b * NSG * NC + c;
    #pragma unroll 8
    for (int sg = 0; sg < NSG; ++sg) wm += satt[sg] * mp[(long long)sg * NC];

    const float* whr = Wh + (long long)c * NCLS;
    #pragma unroll 1
    for (int cls = 0; cls < NCLS; ++cls) {
        float p = wm * whr[cls];
        #pragma unroll
        for (int o = 16; o > 0; o >>= 1) p += __shfl_xor_sync(0xffffffffu, p, o);
        if (lane == 0) atomicAdd(&out[b * NCLS + cls], p);
    }
}

// ============================================================
// Kernel 6: BCE-with-logits loss, mean over all 608 elements.
// ============================================================
__global__ void loss_kernel(const float* __restrict__ target,
                            float* __restrict__ out, int out_size) {
    const int n = NB * NCLS;   // 608
    int t = threadIdx.x;
    float v = 0.0f;
    if (t < n) {
        float l = out[t];
        float tg = target[t];
        v = fmaxf(l, 0.0f) - l * tg + log1pf(expf(-fabsf(l)));
    }
    __shared__ float red[32];
    int lane = t & 31, warp = t >> 5;
    #pragma unroll
    for (int o = 16; o > 0; o >>= 1) v += __shfl_xor_sync(0xffffffffu, v, o);
    if (lane == 0) red[warp] = v;
    __syncthreads();
    if (t < 32) {
        float s = (t < 20) ? red[t] : 0.0f;
        #pragma unroll
        for (int o = 16; o > 0; o >>= 1) s += __shfl_xor_sync(0xffffffffu, s, o);
        if (t == 0) out[out_size - 1] = s / (float)n;
    }
}

// ============================================================
extern "C" void kernel_launch(void* const* d_in, const int* in_sizes, int n_in,
                              void* d_out, int out_size) {
    const float* x      = (const float*)d_in[0];
    const int*   mask   = (const int*)d_in[1];
    const float* target = (const float*)d_in[2];
    const float* Wa1    = (const float*)d_in[3];
    const float* ba1    = (const float*)d_in[4];
    const float* Wa2    = (const float*)d_in[5];
    const float* ba2    = (const float*)d_in[6];
    const float* Wh     = (const float*)d_in[7];
    const float* bh     = (const float*)d_in[8];
    float* out = (float*)d_out;

    cudaFuncSetAttribute(att_gemm_kernel,
                         cudaFuncAttributeMaxDynamicSharedMemorySize, GEMM_SMEM);

    prep_kernel<<<NB, 256>>>(mask);
    zero_att_kernel<<<16, 256>>>(bh, out);
    seg_kernel<<<dim3(16, NB), 256>>>(x);
    att_gemm_kernel<<<dim3(ATTH / GBN, (NB * NSG) / GBM), 256, GEMM_SMEM>>>(Wa1, ba1, Wa2);
    wm_kernel<<<dim3(4, NB), 128>>>(Wh, ba2, out);
    loss_kernel<<<1, 640>>>(target, out, out_size);
}